// round 9
// baseline (speedup 1.0000x reference)
#include <cuda_runtime.h>
#include <cuda_fp16.h>
#include <cstdint>

// ECGGraphNetwork fused: single-term fp16 mma.sync, 256 threads/block.
// R9: 2(M)x4(N) warp grid, NT=8 n8-tiles/warp -> A-ldmatrix redundancy 8x->4x.

#define BATCH    16384
#define NLEADS   12
#define MROWS    96                 // 8 items * 12 leads
#define NTHREADS 256
#define NBLOCKS  (BATCH / 8)        // 2048

#define LDW   264                   // W chunk row stride (halves), 528B
#define LDAX  40                    // X chunk row stride (halves), 80B
#define LDH   264                   // H row stride (halves), 528B
#define OUTLD 264                   // OUT row stride (fp32 elems), 1056B

// smem byte offsets
#define WCH      16896              // one W buffer: 32*528
#define OFFX     33792              // after 2 W buffers
#define XCH      7680               // one X buffer: 96*80
#define OFF_OUT  0                  // aliases chunk region (96*264*4 = 101376)
#define OFF_H    101376             // 96*528 = 50688
#define OFF_ADJ  152064
#define SMEMSZ   152640

// pre-converted fp16 weights, [K][N] row-major, element offsets
__device__ __half g_Wf[229376];
#define WOFF1 0
#define WOFF2 131072
#define WOFF3 196608

// ---------------- PTX helpers ----------------

__device__ __forceinline__ uint32_t smem_u32(const void* p) {
    uint32_t a;
    asm("{ .reg .u64 t; cvta.to.shared.u64 t, %1; cvt.u32.u64 %0, t; }" : "=r"(a) : "l"(p));
    return a;
}

__device__ __forceinline__ void ldsm4(uint32_t* r, uint32_t a) {
    asm volatile("ldmatrix.sync.aligned.m8n8.x4.shared.b16 {%0,%1,%2,%3}, [%4];"
                 : "=r"(r[0]), "=r"(r[1]), "=r"(r[2]), "=r"(r[3]) : "r"(a));
}
__device__ __forceinline__ void ldsm4t(uint32_t* r, uint32_t a) {
    asm volatile("ldmatrix.sync.aligned.m8n8.x4.trans.shared.b16 {%0,%1,%2,%3}, [%4];"
                 : "=r"(r[0]), "=r"(r[1]), "=r"(r[2]), "=r"(r[3]) : "r"(a));
}

__device__ __forceinline__ void mma_fp16(float* d, const uint32_t* a,
                                         uint32_t b0, uint32_t b1) {
    asm volatile(
        "mma.sync.aligned.m16n8k16.row.col.f32.f16.f16.f32 "
        "{%0,%1,%2,%3}, {%4,%5,%6,%7}, {%8,%9}, {%0,%1,%2,%3};"
        : "+f"(d[0]), "+f"(d[1]), "+f"(d[2]), "+f"(d[3])
        : "r"(a[0]), "r"(a[1]), "r"(a[2]), "r"(a[3]), "r"(b0), "r"(b1));
}

__device__ __forceinline__ uint32_t h2u(__half2 h) { return *(uint32_t*)&h; }

// fp32 x4 -> fp16 x4 (packed uint2)
__device__ __forceinline__ uint2 pack_h4(float4 v) {
    uint2 r;
    r.x = h2u(__floats2half2_rn(v.x, v.y));
    r.y = h2u(__floats2half2_rn(v.z, v.w));
    return r;
}

// ---------------- weight fp16 convert kernel ----------------
__global__ void __launch_bounds__(512) wconv(const float* __restrict__ W1,
                                             const float* __restrict__ W2,
                                             const float* __restrict__ W3) {
    int e = (blockIdx.x * 512 + threadIdx.x) * 4;     // 112 blocks -> 229376 exact
    const float* src;
    int off;
    if (e < 131072)      { src = W1; off = e; }
    else if (e < 196608) { src = W2; off = e - 131072; }
    else                 { src = W3; off = e - 196608; }
    float4 v = *(const float4*)(src + off);
    *(uint2*)(g_Wf + e) = pack_h4(v);
}

// ---------------- adjacency ----------------
__device__ __forceinline__ void build_adj(float* As, int tid) {
    if (tid < NLEADS * NLEADS) {
        const unsigned char ci[15] = {0,0,1,0,1,2,0,1,1,2,6,7,8,9,10};
        const unsigned char cj[15] = {1,2,2,3,3,3,4,4,5,5,7,8,9,10,11};
        int i = tid / NLEADS;
        int j = tid - i * NLEADS;
        float a = (i == j) ? 2.0f : 0.0f;
        float degi = 2.0f, degj = 2.0f;
        #pragma unroll
        for (int e = 0; e < 15; e++) {
            int u = ci[e], v = cj[e];
            if ((u == i && v == j) || (u == j && v == i)) a = 1.0f;
            if (u == i || v == i) degi += 1.0f;
            if (u == j || v == j) degj += 1.0f;
        }
        As[tid] = a * rsqrtf(degi) * rsqrtf(degj);
    }
}

// ---------------- k-step: 3 m-tiles x NT n-tiles, single fp16 term ----------------
template<int NT>
__device__ __forceinline__ void kstep_mma(float (*acc)[NT][4],
                                          uint32_t aBase, int ldaB,
                                          uint32_t wBase, int lane)
{
    uint32_t b[2 * NT];
    {
        uint32_t off = (uint32_t)((lane & 15) * (LDW * 2)) + (uint32_t)(((lane >> 4) << 3) * 2);
        #pragma unroll
        for (int j = 0; j < NT / 2; j++)
            ldsm4t(b + 4 * j, wBase + off + (uint32_t)(j * 32));
    }
    uint32_t aoff = (uint32_t)((lane & 15) * ldaB) + (uint32_t)(((lane >> 4) << 3) * 2);
    #pragma unroll
    for (int m = 0; m < 3; m++) {
        uint32_t a[4];
        ldsm4(a, aBase + (uint32_t)(m * 16 * ldaB) + aoff);
        #pragma unroll
        for (int n = 0; n < NT; n++) mma_fp16(acc[m][n], a, b[2*n], b[2*n+1]);
    }
}

// ---------------- one GEMM layer: OUT = A @ W (fp32 result in smem) ----------------
template<int KD, int ND, bool L1>
__device__ __forceinline__ void gemm_layer(char* smem, uint32_t sbase,
                                           const float* __restrict__ Asrc,
                                           const __half* __restrict__ Wf,
                                           int row0)
{
    constexpr int NC   = KD / 32;
    constexpr int NT   = ND / 32;      // n8-tiles per warp (8 or 4)
    constexpr int NG16 = ND / 8;       // 16B granules per W row
    constexpr int G    = 32 * NG16 / NTHREADS;   // granules per thread (4 or 2)
    const int tid = threadIdx.x, lane = tid & 31, wid = tid >> 5;
    const int mw  = wid >> 2, nw = wid & 3;
    const int m0  = mw * 48;
    const int n0  = nw * (ND / 4);

    float acc[3][NT][4] = {};
    uint4 wr[G];
    float4 xr[3];

    // preload chunk 0
    #pragma unroll
    for (int g = 0; g < G; g++) {
        int idx = tid + g * NTHREADS;
        int r = idx / NG16, cc = idx % NG16;
        wr[g] = *(const uint4*)(Wf + (size_t)r * ND + cc * 8);
    }
    if (L1) {
        #pragma unroll
        for (int i = 0; i < 3; i++) {
            int f4 = tid + i * NTHREADS;
            xr[i] = *(const float4*)(Asrc + (size_t)(row0 + (f4 >> 3)) * 512 + (f4 & 7) * 4);
        }
    }

    for (int c = 0; c < NC; c++) {
        const int buf = c & 1;
        // ---- store current chunk ----
        {
            char* wb = smem + buf * WCH;
            #pragma unroll
            for (int g = 0; g < G; g++) {
                int idx = tid + g * NTHREADS;
                int r = idx / NG16, cc = idx % NG16;
                *(uint4*)(wb + r * (LDW * 2) + cc * 16) = wr[g];
            }
            if (L1) {
                char* xb = smem + OFFX + buf * XCH;
                #pragma unroll
                for (int i = 0; i < 3; i++) {
                    int f4 = tid + i * NTHREADS;
                    int off = (f4 >> 3) * (LDAX * 2) + (f4 & 7) * 8;
                    *(uint2*)(xb + off) = pack_h4(xr[i]);
                }
            }
        }
        __syncthreads();
        // ---- prefetch next chunk into regs ----
        if (c + 1 < NC) {
            const __half* Wn = Wf + (size_t)(c + 1) * 32 * ND;
            #pragma unroll
            for (int g = 0; g < G; g++) {
                int idx = tid + g * NTHREADS;
                int r = idx / NG16, cc = idx % NG16;
                wr[g] = *(const uint4*)(Wn + (size_t)r * ND + cc * 8);
            }
            if (L1) {
                #pragma unroll
                for (int i = 0; i < 3; i++) {
                    int f4 = tid + i * NTHREADS;
                    xr[i] = *(const float4*)(Asrc + (size_t)(row0 + (f4 >> 3)) * 512
                                             + (c + 1) * 32 + (f4 & 7) * 4);
                }
            }
        }
        // ---- compute 2 k-steps of 16 ----
        #pragma unroll
        for (int st = 0; st < 2; st++) {
            uint32_t wb = sbase + (uint32_t)(buf * WCH + st * 16 * (LDW * 2) + n0 * 2);
            if (L1) {
                uint32_t ab = sbase + (uint32_t)(OFFX + buf * XCH + m0 * (LDAX * 2) + st * 32);
                kstep_mma<NT>(acc, ab, LDAX * 2, wb, lane);
            } else {
                int kg = c * 32 + st * 16;
                uint32_t ab = sbase + (uint32_t)(OFF_H + m0 * (LDH * 2) + kg * 2);
                kstep_mma<NT>(acc, ab, LDH * 2, wb, lane);
            }
        }
        __syncthreads();
    }

    // ---- epilogue: accum -> OUT (fp32, stride OUTLD) ----
    float* OUT = (float*)(smem + OFF_OUT);
    #pragma unroll
    for (int m = 0; m < 3; m++)
        #pragma unroll
        for (int n = 0; n < NT; n++) {
            int r  = m0 + m * 16 + (lane >> 2);
            int cc = n0 + n * 8 + (lane & 3) * 2;
            *(float2*)(OUT + r * OUTLD + cc)       = make_float2(acc[m][n][0], acc[m][n][1]);
            *(float2*)(OUT + (r + 8) * OUTLD + cc) = make_float2(acc[m][n][2], acc[m][n][3]);
        }
    __syncthreads();
}

// ---------------- mix + relu + fp16 store (N=256), register-blocked ----------------
// Thread = (batch item, column quad); 256 threads -> each covers 2 column quads.
__device__ __forceinline__ void mix_relu(char* smem, const float* __restrict__ bias) {
    const float* As  = (const float*)(smem + OFF_ADJ);
    const float* OUT = (const float*)(smem + OFF_OUT);
    const int item = threadIdx.x >> 5;        // 0..7
    const int c4b  = threadIdx.x & 31;        // 0..31

    #pragma unroll
    for (int h = 0; h < 2; h++) {
        const int c4 = c4b + h * 32;          // 0..63
        float4 v[NLEADS];
        const float* src = OUT + (item * NLEADS) * OUTLD + c4 * 4;
        #pragma unroll
        for (int m = 0; m < NLEADS; m++) v[m] = *(const float4*)(src + m * OUTLD);

        float4 bv = *(const float4*)(bias + c4 * 4);
        char* dst = smem + OFF_H + (item * NLEADS) * (LDH * 2) + c4 * 8;
        #pragma unroll
        for (int n = 0; n < NLEADS; n++) {
            float4 s = bv;
            #pragma unroll
            for (int m = 0; m < NLEADS; m++) {
                float a = As[n * NLEADS + m];
                s.x = fmaf(a, v[m].x, s.x); s.y = fmaf(a, v[m].y, s.y);
                s.z = fmaf(a, v[m].z, s.z); s.w = fmaf(a, v[m].w, s.w);
            }
            s.x = fmaxf(s.x, 0.f); s.y = fmaxf(s.y, 0.f);
            s.z = fmaxf(s.z, 0.f); s.w = fmaxf(s.w, 0.f);
            *(uint2*)(dst + n * (LDH * 2)) = pack_h4(s);
        }
    }
}

// ---------------- layer-3 mix + bias + mean/max pool ----------------
__device__ __forceinline__ void mix_pool(char* smem, const float* __restrict__ bias,
                                         float* __restrict__ out, int bout0) {
    const float* As  = (const float*)(smem + OFF_ADJ);
    const float* OUT = (const float*)(smem + OFF_OUT);
    int b  = threadIdx.x >> 5;      // 0..7
    int c4 = threadIdx.x & 31;      // 0..31 (128/4)
    float4 v[NLEADS];
    #pragma unroll
    for (int m = 0; m < NLEADS; m++)
        v[m] = *(const float4*)(OUT + (b * NLEADS + m) * OUTLD + c4 * 4);
    float4 bv = *(const float4*)(bias + c4 * 4);
    float4 sum = make_float4(0.f, 0.f, 0.f, 0.f);
    float4 mx  = make_float4(-3.4e38f, -3.4e38f, -3.4e38f, -3.4e38f);
    #pragma unroll
    for (int r = 0; r < NLEADS; r++) {
        float4 s = bv;
        #pragma unroll
        for (int m = 0; m < NLEADS; m++) {
            float a = As[r * NLEADS + m];
            s.x = fmaf(a, v[m].x, s.x); s.y = fmaf(a, v[m].y, s.y);
            s.z = fmaf(a, v[m].z, s.z); s.w = fmaf(a, v[m].w, s.w);
        }
        sum.x += s.x; sum.y += s.y; sum.z += s.z; sum.w += s.w;
        mx.x = fmaxf(mx.x, s.x); mx.y = fmaxf(mx.y, s.y);
        mx.z = fmaxf(mx.z, s.z); mx.w = fmaxf(mx.w, s.w);
    }
    const float inv = 1.0f / 12.0f;
    float* op = out + (size_t)(bout0 + b) * 256;
    *(float4*)(op + c4 * 4)       = make_float4(sum.x*inv, sum.y*inv, sum.z*inv, sum.w*inv);
    *(float4*)(op + 128 + c4 * 4) = mx;
}

// ---------------- kernel ----------------
__global__ void __launch_bounds__(NTHREADS, 1)
ecg_mma(const float* __restrict__ x,
        const float* __restrict__ b1, const float* __restrict__ b2,
        const float* __restrict__ b3, float* __restrict__ out)
{
    extern __shared__ char smem[];
    const uint32_t sbase = smem_u32(smem);
    const int row0  = blockIdx.x * MROWS;
    const int bout0 = blockIdx.x * 8;

    build_adj((float*)(smem + OFF_ADJ), threadIdx.x);

    // layer 1: X(96x512) @ W1(512x256)
    gemm_layer<512, 256, true>(smem, sbase, x, g_Wf + WOFF1, row0);
    mix_relu(smem, b1);
    __syncthreads();
    // layer 2: H(96x256) @ W2(256x256)
    gemm_layer<256, 256, false>(smem, sbase, nullptr, g_Wf + WOFF2, row0);
    mix_relu(smem, b2);
    __syncthreads();
    // layer 3: H(96x256) @ W3(256x128) + mix + pool
    gemm_layer<256, 128, false>(smem, sbase, nullptr, g_Wf + WOFF3, row0);
    mix_pool(smem, b3, out, bout0);
}

// ---------------- launch ----------------
extern "C" void kernel_launch(void* const* d_in, const int* in_sizes, int n_in,
                              void* d_out, int out_size)
{
    const float* x  = (const float*)d_in[0];
    const float* W1 = (const float*)d_in[1];
    const float* b1 = (const float*)d_in[2];
    const float* W2 = (const float*)d_in[3];
    const float* b2 = (const float*)d_in[4];
    const float* W3 = (const float*)d_in[5];
    const float* b3 = (const float*)d_in[6];
    float* out = (float*)d_out;

    wconv<<<112, 512>>>(W1, W2, W3);

    cudaFuncSetAttribute((const void*)ecg_mma,
                         cudaFuncAttributeMaxDynamicSharedMemorySize, SMEMSZ);
    ecg_mma<<<NBLOCKS, NTHREADS, SMEMSZ>>>(x, b1, b2, b3, out);
}

// round 10
// speedup vs baseline: 1.0923x; 1.0923x over previous
#include <cuda_runtime.h>
#include <cuda_fp16.h>
#include <cstdint>

// ECGGraphNetwork fused: single-term fp16 mma.sync, 512 threads/block.
// R10 = R8 (best: 411us) + software-pipelined chunk loop: STS of chunk c+1
// overlaps MMA of chunk c; one __syncthreads per chunk instead of two.

#define BATCH    16384
#define NLEADS   12
#define MROWS    96                 // 8 items * 12 leads
#define NTHREADS 512
#define NBLOCKS  (BATCH / 8)        // 2048

#define LDW   264                   // W chunk row stride (halves), 528B
#define LDAX  40                    // X chunk row stride (halves), 80B
#define LDH   264                   // H row stride (halves), 528B
#define OUTLD 264                   // OUT row stride (fp32 elems), 1056B

// smem byte offsets
#define WCH      16896              // one W buffer: 32*528
#define OFFX     33792              // after 2 W buffers
#define XCH      7680               // one X buffer: 96*80
#define OFF_OUT  0                  // aliases chunk region (96*264*4 = 101376)
#define OFF_H    101376             // 96*528 = 50688
#define OFF_ADJ  152064
#define SMEMSZ   152640

// pre-converted fp16 weights, [K][N] row-major, element offsets
__device__ __half g_Wf[229376];
#define WOFF1 0
#define WOFF2 131072
#define WOFF3 196608

// ---------------- PTX helpers ----------------

__device__ __forceinline__ uint32_t smem_u32(const void* p) {
    uint32_t a;
    asm("{ .reg .u64 t; cvta.to.shared.u64 t, %1; cvt.u32.u64 %0, t; }" : "=r"(a) : "l"(p));
    return a;
}

__device__ __forceinline__ void ldsm4(uint32_t* r, uint32_t a) {
    asm volatile("ldmatrix.sync.aligned.m8n8.x4.shared.b16 {%0,%1,%2,%3}, [%4];"
                 : "=r"(r[0]), "=r"(r[1]), "=r"(r[2]), "=r"(r[3]) : "r"(a));
}
__device__ __forceinline__ void ldsm4t(uint32_t* r, uint32_t a) {
    asm volatile("ldmatrix.sync.aligned.m8n8.x4.trans.shared.b16 {%0,%1,%2,%3}, [%4];"
                 : "=r"(r[0]), "=r"(r[1]), "=r"(r[2]), "=r"(r[3]) : "r"(a));
}

__device__ __forceinline__ void mma_fp16(float* d, const uint32_t* a,
                                         uint32_t b0, uint32_t b1) {
    asm volatile(
        "mma.sync.aligned.m16n8k16.row.col.f32.f16.f16.f32 "
        "{%0,%1,%2,%3}, {%4,%5,%6,%7}, {%8,%9}, {%0,%1,%2,%3};"
        : "+f"(d[0]), "+f"(d[1]), "+f"(d[2]), "+f"(d[3])
        : "r"(a[0]), "r"(a[1]), "r"(a[2]), "r"(a[3]), "r"(b0), "r"(b1));
}

__device__ __forceinline__ uint32_t h2u(__half2 h) { return *(uint32_t*)&h; }

// fp32 x4 -> fp16 x4 (packed uint2)
__device__ __forceinline__ uint2 pack_h4(float4 v) {
    uint2 r;
    r.x = h2u(__floats2half2_rn(v.x, v.y));
    r.y = h2u(__floats2half2_rn(v.z, v.w));
    return r;
}

// ---------------- weight fp16 convert kernel ----------------
__global__ void __launch_bounds__(512) wconv(const float* __restrict__ W1,
                                             const float* __restrict__ W2,
                                             const float* __restrict__ W3) {
    int e = (blockIdx.x * 512 + threadIdx.x) * 4;     // 112 blocks -> 229376 exact
    const float* src;
    int off;
    if (e < 131072)      { src = W1; off = e; }
    else if (e < 196608) { src = W2; off = e - 131072; }
    else                 { src = W3; off = e - 196608; }
    float4 v = *(const float4*)(src + off);
    *(uint2*)(g_Wf + e) = pack_h4(v);
}

// ---------------- adjacency ----------------
__device__ __forceinline__ void build_adj(float* As, int tid) {
    if (tid < NLEADS * NLEADS) {
        const unsigned char ci[15] = {0,0,1,0,1,2,0,1,1,2,6,7,8,9,10};
        const unsigned char cj[15] = {1,2,2,3,3,3,4,4,5,5,7,8,9,10,11};
        int i = tid / NLEADS;
        int j = tid - i * NLEADS;
        float a = (i == j) ? 2.0f : 0.0f;
        float degi = 2.0f, degj = 2.0f;
        #pragma unroll
        for (int e = 0; e < 15; e++) {
            int u = ci[e], v = cj[e];
            if ((u == i && v == j) || (u == j && v == i)) a = 1.0f;
            if (u == i || v == i) degi += 1.0f;
            if (u == j || v == j) degj += 1.0f;
        }
        As[tid] = a * rsqrtf(degi) * rsqrtf(degj);
    }
}

// ---------------- k-step: 3 m-tiles x NT n-tiles, single fp16 term ----------------
template<int NT>
__device__ __forceinline__ void kstep_mma(float (*acc)[NT][4],
                                          uint32_t aBase, int ldaB,
                                          uint32_t wBase, int lane)
{
    uint32_t b[2 * NT];
    {
        uint32_t off = (uint32_t)((lane & 15) * (LDW * 2)) + (uint32_t)(((lane >> 4) << 3) * 2);
        ldsm4t(b, wBase + off);
        if (NT == 4) ldsm4t(b + 4, wBase + off + 32);
    }
    uint32_t aoff = (uint32_t)((lane & 15) * ldaB) + (uint32_t)(((lane >> 4) << 3) * 2);
    #pragma unroll
    for (int m = 0; m < 3; m++) {
        uint32_t a[4];
        ldsm4(a, aBase + (uint32_t)(m * 16 * ldaB) + aoff);
        #pragma unroll
        for (int n = 0; n < NT; n++) mma_fp16(acc[m][n], a, b[2*n], b[2*n+1]);
    }
}

// ---------------- one GEMM layer: OUT = A @ W (fp32 result in smem) ----------------
// Pipelined: STS of chunk c+1 overlaps MMA of chunk c; one sync per chunk.
template<int KD, int ND, bool L1>
__device__ __forceinline__ void gemm_layer(char* smem, uint32_t sbase,
                                           const float* __restrict__ Asrc,
                                           const __half* __restrict__ Wf,
                                           int row0)
{
    constexpr int NC   = KD / 32;
    constexpr int NT   = ND / 64;      // n8-tiles per warp (4 or 2)
    constexpr int NG16 = ND / 8;       // 16B granules per W row
    constexpr int G    = 32 * NG16 / NTHREADS;   // granules per thread (2 or 1)
    const int tid = threadIdx.x, lane = tid & 31, wid = tid >> 5;
    const int mw  = wid >> 3, nw = wid & 7;
    const int m0  = mw * 48;
    const int n0  = nw * (ND / 8);

    float acc[3][NT][4] = {};
    uint4 wr[G];
    float4 xr[2];

    auto ldgW = [&](int c) {
        const __half* Wc = Wf + (size_t)c * 32 * ND;
        #pragma unroll
        for (int g = 0; g < G; g++) {
            int idx = tid + g * NTHREADS;
            int r = idx / NG16, cc = idx % NG16;
            wr[g] = *(const uint4*)(Wc + (size_t)r * ND + cc * 8);
        }
    };
    auto stsW = [&](int buf) {
        char* wb = smem + buf * WCH;
        #pragma unroll
        for (int g = 0; g < G; g++) {
            int idx = tid + g * NTHREADS;
            int r = idx / NG16, cc = idx % NG16;
            *(uint4*)(wb + r * (LDW * 2) + cc * 16) = wr[g];
        }
    };
    auto ldgX = [&](int c) {
        #pragma unroll
        for (int i = 0; i < 2; i++) {
            int f4 = tid + i * NTHREADS;
            if (f4 < MROWS * 8)
                xr[i] = *(const float4*)(Asrc + (size_t)(row0 + (f4 >> 3)) * 512
                                         + c * 32 + (f4 & 7) * 4);
        }
    };
    auto stsX = [&](int buf) {
        char* xb = smem + OFFX + buf * XCH;
        #pragma unroll
        for (int i = 0; i < 2; i++) {
            int f4 = tid + i * NTHREADS;
            if (f4 < MROWS * 8) {
                int off = (f4 >> 3) * (LDAX * 2) + (f4 & 7) * 8;
                *(uint2*)(xb + off) = pack_h4(xr[i]);
            }
        }
    };

    // prologue: chunk 0 into buf0
    ldgW(0);
    if (L1) ldgX(0);
    stsW(0);
    if (L1) stsX(0);
    __syncthreads();
    if (NC > 1) { ldgW(1); if (L1) ldgX(1); }

    for (int c = 0; c < NC; c++) {
        const int buf = c & 1;
        // stage chunk c+1 into the other buffer (overlaps this chunk's MMAs)
        if (c + 1 < NC) {
            stsW(buf ^ 1);
            if (L1) stsX(buf ^ 1);
            if (c + 2 < NC) { ldgW(c + 2); if (L1) ldgX(c + 2); }
        }
        // compute 2 k-steps of 16 from buf
        #pragma unroll
        for (int st = 0; st < 2; st++) {
            uint32_t wb = sbase + (uint32_t)(buf * WCH + st * 16 * (LDW * 2) + n0 * 2);
            if (L1) {
                uint32_t ab = sbase + (uint32_t)(OFFX + buf * XCH + m0 * (LDAX * 2) + st * 32);
                kstep_mma<NT>(acc, ab, LDAX * 2, wb, lane);
            } else {
                int kg = c * 32 + st * 16;
                uint32_t ab = sbase + (uint32_t)(OFF_H + m0 * (LDH * 2) + kg * 2);
                kstep_mma<NT>(acc, ab, LDH * 2, wb, lane);
            }
        }
        __syncthreads();
    }

    // ---- epilogue: accum -> OUT (fp32, stride OUTLD) ----
    float* OUT = (float*)(smem + OFF_OUT);
    #pragma unroll
    for (int m = 0; m < 3; m++)
        #pragma unroll
        for (int n = 0; n < NT; n++) {
            int r  = m0 + m * 16 + (lane >> 2);
            int cc = n0 + n * 8 + (lane & 3) * 2;
            *(float2*)(OUT + r * OUTLD + cc)       = make_float2(acc[m][n][0], acc[m][n][1]);
            *(float2*)(OUT + (r + 8) * OUTLD + cc) = make_float2(acc[m][n][2], acc[m][n][3]);
        }
    __syncthreads();
}

// ---------------- mix + relu + fp16 store (N=256), register-blocked ----------------
__device__ __forceinline__ void mix_relu(char* smem, const float* __restrict__ bias) {
    const float* As  = (const float*)(smem + OFF_ADJ);
    const float* OUT = (const float*)(smem + OFF_OUT);
    const int item = threadIdx.x >> 6;    // 0..7
    const int c4   = threadIdx.x & 63;    // 0..63

    float4 v[NLEADS];
    const float* src = OUT + (item * NLEADS) * OUTLD + c4 * 4;
    #pragma unroll
    for (int m = 0; m < NLEADS; m++) v[m] = *(const float4*)(src + m * OUTLD);

    float4 bv = *(const float4*)(bias + c4 * 4);
    char* dst = smem + OFF_H + (item * NLEADS) * (LDH * 2) + c4 * 8;
    #pragma unroll
    for (int n = 0; n < NLEADS; n++) {
        float4 s = bv;
        #pragma unroll
        for (int m = 0; m < NLEADS; m++) {
            float a = As[n * NLEADS + m];
            s.x = fmaf(a, v[m].x, s.x); s.y = fmaf(a, v[m].y, s.y);
            s.z = fmaf(a, v[m].z, s.z); s.w = fmaf(a, v[m].w, s.w);
        }
        s.x = fmaxf(s.x, 0.f); s.y = fmaxf(s.y, 0.f);
        s.z = fmaxf(s.z, 0.f); s.w = fmaxf(s.w, 0.f);
        *(uint2*)(dst + n * (LDH * 2)) = pack_h4(s);
    }
}

// ---------------- layer-3 mix + bias + mean/max pool ----------------
__device__ __forceinline__ void mix_pool(char* smem, const float* __restrict__ bias,
                                         float* __restrict__ out, int bout0) {
    if (threadIdx.x >= 256) return;
    const float* As  = (const float*)(smem + OFF_ADJ);
    const float* OUT = (const float*)(smem + OFF_OUT);
    int b  = threadIdx.x >> 5;      // 0..7
    int c4 = threadIdx.x & 31;      // 0..31 (128/4)
    float4 v[NLEADS];
    #pragma unroll
    for (int m = 0; m < NLEADS; m++)
        v[m] = *(const float4*)(OUT + (b * NLEADS + m) * OUTLD + c4 * 4);
    float4 bv = *(const float4*)(bias + c4 * 4);
    float4 sum = make_float4(0.f, 0.f, 0.f, 0.f);
    float4 mx  = make_float4(-3.4e38f, -3.4e38f, -3.4e38f, -3.4e38f);
    #pragma unroll
    for (int r = 0; r < NLEADS; r++) {
        float4 s = bv;
        #pragma unroll
        for (int m = 0; m < NLEADS; m++) {
            float a = As[r * NLEADS + m];
            s.x = fmaf(a, v[m].x, s.x); s.y = fmaf(a, v[m].y, s.y);
            s.z = fmaf(a, v[m].z, s.z); s.w = fmaf(a, v[m].w, s.w);
        }
        sum.x += s.x; sum.y += s.y; sum.z += s.z; sum.w += s.w;
        mx.x = fmaxf(mx.x, s.x); mx.y = fmaxf(mx.y, s.y);
        mx.z = fmaxf(mx.z, s.z); mx.w = fmaxf(mx.w, s.w);
    }
    const float inv = 1.0f / 12.0f;
    float* op = out + (size_t)(bout0 + b) * 256;
    *(float4*)(op + c4 * 4)       = make_float4(sum.x*inv, sum.y*inv, sum.z*inv, sum.w*inv);
    *(float4*)(op + 128 + c4 * 4) = mx;
}

// ---------------- kernel ----------------
__global__ void __launch_bounds__(NTHREADS, 1)
ecg_mma(const float* __restrict__ x,
        const float* __restrict__ b1, const float* __restrict__ b2,
        const float* __restrict__ b3, float* __restrict__ out)
{
    extern __shared__ char smem[];
    const uint32_t sbase = smem_u32(smem);
    const int row0  = blockIdx.x * MROWS;
    const int bout0 = blockIdx.x * 8;

    build_adj((float*)(smem + OFF_ADJ), threadIdx.x);

    // layer 1: X(96x512) @ W1(512x256)
    gemm_layer<512, 256, true>(smem, sbase, x, g_Wf + WOFF1, row0);
    mix_relu(smem, b1);
    __syncthreads();
    // layer 2: H(96x256) @ W2(256x256)
    gemm_layer<256, 256, false>(smem, sbase, nullptr, g_Wf + WOFF2, row0);
    mix_relu(smem, b2);
    __syncthreads();
    // layer 3: H(96x256) @ W3(256x128) + mix + pool
    gemm_layer<256, 128, false>(smem, sbase, nullptr, g_Wf + WOFF3, row0);
    mix_pool(smem, b3, out, bout0);
}

// ---------------- launch ----------------
extern "C" void kernel_launch(void* const* d_in, const int* in_sizes, int n_in,
                              void* d_out, int out_size)
{
    const float* x  = (const float*)d_in[0];
    const float* W1 = (const float*)d_in[1];
    const float* b1 = (const float*)d_in[2];
    const float* W2 = (const float*)d_in[3];
    const float* b2 = (const float*)d_in[4];
    const float* W3 = (const float*)d_in[5];
    const float* b3 = (const float*)d_in[6];
    float* out = (float*)d_out;

    wconv<<<112, 512>>>(W1, W2, W3);

    cudaFuncSetAttribute((const void*)ecg_mma,
                         cudaFuncAttributeMaxDynamicSharedMemorySize, SMEMSZ);
    ecg_mma<<<NBLOCKS, NTHREADS, SMEMSZ>>>(x, b1, b2, b3, out);
}

// round 13
// speedup vs baseline: 1.2134x; 1.1108x over previous
#include <cuda_runtime.h>
#include <cuda_fp16.h>
#include <cstdint>

// ECGGraphNetwork fused: single-term fp16 mma.sync, 512 threads/block.
// R11 = R10 + sparse graph-mix: the fixed 12-lead adjacency has 42/144
// nonzeros; skip exact-zero terms (bitwise-identical result, 3.4x fewer FMAs).

#define BATCH    16384
#define NLEADS   12
#define MROWS    96                 // 8 items * 12 leads
#define NTHREADS 512
#define NBLOCKS  (BATCH / 8)        // 2048

#define LDW   264                   // W chunk row stride (halves), 528B
#define LDAX  40                    // X chunk row stride (halves), 80B
#define LDH   264                   // H row stride (halves), 528B
#define OUTLD 264                   // OUT row stride (fp32 elems), 1056B

// smem byte offsets
#define WCH      16896              // one W buffer: 32*528
#define OFFX     33792              // after 2 W buffers
#define XCH      7680               // one X buffer: 96*80
#define OFF_OUT  0                  // aliases chunk region (96*264*4 = 101376)
#define OFF_H    101376             // 96*528 = 50688
#define OFF_ADJ  152064
#define SMEMSZ   152640

// pre-converted fp16 weights, [K][N] row-major, element offsets
__device__ __half g_Wf[229376];
#define WOFF1 0
#define WOFF2 131072
#define WOFF3 196608

// sparsity of A_norm (fixed ECG graph): per-row nonzero column indices (ascending)
#define MIX_TABLES \
    const int mcnt[12] = {5,6,5,4,3,3,2,3,3,3,3,2}; \
    const int midx[12][6] = { \
        {0,1,2,3,4,0}, {0,1,2,3,4,5}, {0,1,2,3,5,0}, {0,1,2,3,0,0}, \
        {0,1,4,0,0,0}, {1,2,5,0,0,0}, {6,7,0,0,0,0}, {6,7,8,0,0,0}, \
        {7,8,9,0,0,0}, {8,9,10,0,0,0}, {9,10,11,0,0,0}, {10,11,0,0,0,0} };

// ---------------- PTX helpers ----------------

__device__ __forceinline__ uint32_t smem_u32(const void* p) {
    uint32_t a;
    asm("{ .reg .u64 t; cvta.to.shared.u64 t, %1; cvt.u32.u64 %0, t; }" : "=r"(a) : "l"(p));
    return a;
}

__device__ __forceinline__ void ldsm4(uint32_t* r, uint32_t a) {
    asm volatile("ldmatrix.sync.aligned.m8n8.x4.shared.b16 {%0,%1,%2,%3}, [%4];"
                 : "=r"(r[0]), "=r"(r[1]), "=r"(r[2]), "=r"(r[3]) : "r"(a));
}
__device__ __forceinline__ void ldsm4t(uint32_t* r, uint32_t a) {
    asm volatile("ldmatrix.sync.aligned.m8n8.x4.trans.shared.b16 {%0,%1,%2,%3}, [%4];"
                 : "=r"(r[0]), "=r"(r[1]), "=r"(r[2]), "=r"(r[3]) : "r"(a));
}

__device__ __forceinline__ void mma_fp16(float* d, const uint32_t* a,
                                         uint32_t b0, uint32_t b1) {
    asm volatile(
        "mma.sync.aligned.m16n8k16.row.col.f32.f16.f16.f32 "
        "{%0,%1,%2,%3}, {%4,%5,%6,%7}, {%8,%9}, {%0,%1,%2,%3};"
        : "+f"(d[0]), "+f"(d[1]), "+f"(d[2]), "+f"(d[3])
        : "r"(a[0]), "r"(a[1]), "r"(a[2]), "r"(a[3]), "r"(b0), "r"(b1));
}

__device__ __forceinline__ uint32_t h2u(__half2 h) { return *(uint32_t*)&h; }

// fp32 x4 -> fp16 x4 (packed uint2)
__device__ __forceinline__ uint2 pack_h4(float4 v) {
    uint2 r;
    r.x = h2u(__floats2half2_rn(v.x, v.y));
    r.y = h2u(__floats2half2_rn(v.z, v.w));
    return r;
}

// ---------------- weight fp16 convert kernel ----------------
__global__ void __launch_bounds__(512) wconv(const float* __restrict__ W1,
                                             const float* __restrict__ W2,
                                             const float* __restrict__ W3) {
    int e = (blockIdx.x * 512 + threadIdx.x) * 4;     // 112 blocks -> 229376 exact
    const float* src;
    int off;
    if (e < 131072)      { src = W1; off = e; }
    else if (e < 196608) { src = W2; off = e - 131072; }
    else                 { src = W3; off = e - 196608; }
    float4 v = *(const float4*)(src + off);
    *(uint2*)(g_Wf + e) = pack_h4(v);
}

// ---------------- adjacency ----------------
__device__ __forceinline__ void build_adj(float* As, int tid) {
    if (tid < NLEADS * NLEADS) {
        const unsigned char ci[15] = {0,0,1,0,1,2,0,1,1,2,6,7,8,9,10};
        const unsigned char cj[15] = {1,2,2,3,3,3,4,4,5,5,7,8,9,10,11};
        int i = tid / NLEADS;
        int j = tid - i * NLEADS;
        float a = (i == j) ? 2.0f : 0.0f;
        float degi = 2.0f, degj = 2.0f;
        #pragma unroll
        for (int e = 0; e < 15; e++) {
            int u = ci[e], v = cj[e];
            if ((u == i && v == j) || (u == j && v == i)) a = 1.0f;
            if (u == i || v == i) degi += 1.0f;
            if (u == j || v == j) degj += 1.0f;
        }
        As[tid] = a * rsqrtf(degi) * rsqrtf(degj);
    }
}

// ---------------- k-step: 3 m-tiles x NT n-tiles, single fp16 term ----------------
template<int NT>
__device__ __forceinline__ void kstep_mma(float (*acc)[NT][4],
                                          uint32_t aBase, int ldaB,
                                          uint32_t wBase, int lane)
{
    uint32_t b[2 * NT];
    {
        uint32_t off = (uint32_t)((lane & 15) * (LDW * 2)) + (uint32_t)(((lane >> 4) << 3) * 2);
        ldsm4t(b, wBase + off);
        if (NT == 4) ldsm4t(b + 4, wBase + off + 32);
    }
    uint32_t aoff = (uint32_t)((lane & 15) * ldaB) + (uint32_t)(((lane >> 4) << 3) * 2);
    #pragma unroll
    for (int m = 0; m < 3; m++) {
        uint32_t a[4];
        ldsm4(a, aBase + (uint32_t)(m * 16 * ldaB) + aoff);
        #pragma unroll
        for (int n = 0; n < NT; n++) mma_fp16(acc[m][n], a, b[2*n], b[2*n+1]);
    }
}

// ---------------- one GEMM layer: OUT = A @ W (fp32 result in smem) ----------------
// Pipelined: STS of chunk c+1 overlaps MMA of chunk c; one sync per chunk.
template<int KD, int ND, bool L1>
__device__ __forceinline__ void gemm_layer(char* smem, uint32_t sbase,
                                           const float* __restrict__ Asrc,
                                           const __half* __restrict__ Wf,
                                           int row0)
{
    constexpr int NC   = KD / 32;
    constexpr int NT   = ND / 64;      // n8-tiles per warp (4 or 2)
    constexpr int NG16 = ND / 8;       // 16B granules per W row
    constexpr int G    = 32 * NG16 / NTHREADS;   // granules per thread (2 or 1)
    const int tid = threadIdx.x, lane = tid & 31, wid = tid >> 5;
    const int mw  = wid >> 3, nw = wid & 7;
    const int m0  = mw * 48;
    const int n0  = nw * (ND / 8);

    float acc[3][NT][4] = {};
    uint4 wr[G];
    float4 xr[2];

    auto ldgW = [&](int c) {
        const __half* Wc = Wf + (size_t)c * 32 * ND;
        #pragma unroll
        for (int g = 0; g < G; g++) {
            int idx = tid + g * NTHREADS;
            int r = idx / NG16, cc = idx % NG16;
            wr[g] = *(const uint4*)(Wc + (size_t)r * ND + cc * 8);
        }
    };
    auto stsW = [&](int buf) {
        char* wb = smem + buf * WCH;
        #pragma unroll
        for (int g = 0; g < G; g++) {
            int idx = tid + g * NTHREADS;
            int r = idx / NG16, cc = idx % NG16;
            *(uint4*)(wb + r * (LDW * 2) + cc * 16) = wr[g];
        }
    };
    auto ldgX = [&](int c) {
        #pragma unroll
        for (int i = 0; i < 2; i++) {
            int f4 = tid + i * NTHREADS;
            if (f4 < MROWS * 8)
                xr[i] = *(const float4*)(Asrc + (size_t)(row0 + (f4 >> 3)) * 512
                                         + c * 32 + (f4 & 7) * 4);
        }
    };
    auto stsX = [&](int buf) {
        char* xb = smem + OFFX + buf * XCH;
        #pragma unroll
        for (int i = 0; i < 2; i++) {
            int f4 = tid + i * NTHREADS;
            if (f4 < MROWS * 8) {
                int off = (f4 >> 3) * (LDAX * 2) + (f4 & 7) * 8;
                *(uint2*)(xb + off) = pack_h4(xr[i]);
            }
        }
    };

    // prologue: chunk 0 into buf0
    ldgW(0);
    if (L1) ldgX(0);
    stsW(0);
    if (L1) stsX(0);
    __syncthreads();
    if (NC > 1) { ldgW(1); if (L1) ldgX(1); }

    for (int c = 0; c < NC; c++) {
        const int buf = c & 1;
        // stage chunk c+1 into the other buffer (overlaps this chunk's MMAs)
        if (c + 1 < NC) {
            stsW(buf ^ 1);
            if (L1) stsX(buf ^ 1);
            if (c + 2 < NC) { ldgW(c + 2); if (L1) ldgX(c + 2); }
        }
        // compute 2 k-steps of 16 from buf
        #pragma unroll
        for (int st = 0; st < 2; st++) {
            uint32_t wb = sbase + (uint32_t)(buf * WCH + st * 16 * (LDW * 2) + n0 * 2);
            if (L1) {
                uint32_t ab = sbase + (uint32_t)(OFFX + buf * XCH + m0 * (LDAX * 2) + st * 32);
                kstep_mma<NT>(acc, ab, LDAX * 2, wb, lane);
            } else {
                int kg = c * 32 + st * 16;
                uint32_t ab = sbase + (uint32_t)(OFF_H + m0 * (LDH * 2) + kg * 2);
                kstep_mma<NT>(acc, ab, LDH * 2, wb, lane);
            }
        }
        __syncthreads();
    }

    // ---- epilogue: accum -> OUT (fp32, stride OUTLD) ----
    float* OUT = (float*)(smem + OFF_OUT);
    #pragma unroll
    for (int m = 0; m < 3; m++)
        #pragma unroll
        for (int n = 0; n < NT; n++) {
            int r  = m0 + m * 16 + (lane >> 2);
            int cc = n0 + n * 8 + (lane & 3) * 2;
            *(float2*)(OUT + r * OUTLD + cc)       = make_float2(acc[m][n][0], acc[m][n][1]);
            *(float2*)(OUT + (r + 8) * OUTLD + cc) = make_float2(acc[m][n][2], acc[m][n][3]);
        }
    __syncthreads();
}

// ---------------- mix + relu + fp16 store (N=256), register-blocked, sparse ----------------
__device__ __forceinline__ void mix_relu(char* smem, const float* __restrict__ bias) {
    MIX_TABLES
    const float* As  = (const float*)(smem + OFF_ADJ);
    const float* OUT = (const float*)(smem + OFF_OUT);
    const int item = threadIdx.x >> 6;    // 0..7
    const int c4   = threadIdx.x & 63;    // 0..63

    float4 v[NLEADS];
    const float* src = OUT + (item * NLEADS) * OUTLD + c4 * 4;
    #pragma unroll
    for (int m = 0; m < NLEADS; m++) v[m] = *(const float4*)(src + m * OUTLD);

    float4 bv = *(const float4*)(bias + c4 * 4);
    char* dst = smem + OFF_H + (item * NLEADS) * (LDH * 2) + c4 * 8;
    #pragma unroll
    for (int n = 0; n < NLEADS; n++) {
        float4 s = bv;
        #pragma unroll
        for (int t = 0; t < 6; t++) {
            if (t < mcnt[n]) {
                int m = midx[n][t];
                float a = As[n * NLEADS + m];
                s.x = fmaf(a, v[m].x, s.x); s.y = fmaf(a, v[m].y, s.y);
                s.z = fmaf(a, v[m].z, s.z); s.w = fmaf(a, v[m].w, s.w);
            }
        }
        s.x = fmaxf(s.x, 0.f); s.y = fmaxf(s.y, 0.f);
        s.z = fmaxf(s.z, 0.f); s.w = fmaxf(s.w, 0.f);
        *(uint2*)(dst + n * (LDH * 2)) = pack_h4(s);
    }
}

// ---------------- layer-3 mix + bias + mean/max pool (sparse) ----------------
__device__ __forceinline__ void mix_pool(char* smem, const float* __restrict__ bias,
                                         float* __restrict__ out, int bout0) {
    if (threadIdx.x >= 256) return;
    MIX_TABLES
    const float* As  = (const float*)(smem + OFF_ADJ);
    const float* OUT = (const float*)(smem + OFF_OUT);
    int b  = threadIdx.x >> 5;      // 0..7
    int c4 = threadIdx.x & 31;      // 0..31 (128/4)
    float4 v[NLEADS];
    #pragma unroll
    for (int m = 0; m < NLEADS; m++)
        v[m] = *(const float4*)(OUT + (b * NLEADS + m) * OUTLD + c4 * 4);
    float4 bv = *(const float4*)(bias + c4 * 4);
    float4 sum = make_float4(0.f, 0.f, 0.f, 0.f);
    float4 mx  = make_float4(-3.4e38f, -3.4e38f, -3.4e38f, -3.4e38f);
    #pragma unroll
    for (int r = 0; r < NLEADS; r++) {
        float4 s = bv;
        #pragma unroll
        for (int t = 0; t < 6; t++) {
            if (t < mcnt[r]) {
                int m = midx[r][t];
                float a = As[r * NLEADS + m];
                s.x = fmaf(a, v[m].x, s.x); s.y = fmaf(a, v[m].y, s.y);
                s.z = fmaf(a, v[m].z, s.z); s.w = fmaf(a, v[m].w, s.w);
            }
        }
        sum.x += s.x; sum.y += s.y; sum.z += s.z; sum.w += s.w;
        mx.x = fmaxf(mx.x, s.x); mx.y = fmaxf(mx.y, s.y);
        mx.z = fmaxf(mx.z, s.z); mx.w = fmaxf(mx.w, s.w);
    }
    const float inv = 1.0f / 12.0f;
    float* op = out + (size_t)(bout0 + b) * 256;
    *(float4*)(op + c4 * 4)       = make_float4(sum.x*inv, sum.y*inv, sum.z*inv, sum.w*inv);
    *(float4*)(op + 128 + c4 * 4) = mx;
}

// ---------------- kernel ----------------
__global__ void __launch_bounds__(NTHREADS, 1)
ecg_mma(const float* __restrict__ x,
        const float* __restrict__ b1, const float* __restrict__ b2,
        const float* __restrict__ b3, float* __restrict__ out)
{
    extern __shared__ char smem[];
    const uint32_t sbase = smem_u32(smem);
    const int row0  = blockIdx.x * MROWS;
    const int bout0 = blockIdx.x * 8;

    build_adj((float*)(smem + OFF_ADJ), threadIdx.x);

    // layer 1: X(96x512) @ W1(512x256)
    gemm_layer<512, 256, true>(smem, sbase, x, g_Wf + WOFF1, row0);
    mix_relu(smem, b1);
    __syncthreads();
    // layer 2: H(96x256) @ W2(256x256)
    gemm_layer<256, 256, false>(smem, sbase, nullptr, g_Wf + WOFF2, row0);
    mix_relu(smem, b2);
    __syncthreads();
    // layer 3: H(96x256) @ W3(256x128) + mix + pool
    gemm_layer<256, 128, false>(smem, sbase, nullptr, g_Wf + WOFF3, row0);
    mix_pool(smem, b3, out, bout0);
}

// ---------------- launch ----------------
extern "C" void kernel_launch(void* const* d_in, const int* in_sizes, int n_in,
                              void* d_out, int out_size)
{
    const float* x  = (const float*)d_in[0];
    const float* W1 = (const float*)d_in[1];
    const float* b1 = (const float*)d_in[2];
    const float* W2 = (const float*)d_in[3];
    const float* b2 = (const float*)d_in[4];
    const float* W3 = (const float*)d_in[5];
    const float* b3 = (const float*)d_in[6];
    float* out = (float*)d_out;

    wconv<<<112, 512>>>(W1, W2, W3);

    cudaFuncSetAttribute((const void*)ecg_mma,
                         cudaFuncAttributeMaxDynamicSharedMemorySize, SMEMSZ);
    ecg_mma<<<NBLOCKS, NTHREADS, SMEMSZ>>>(x, b1, b2, b3, out);
}

// round 15
// speedup vs baseline: 1.2551x; 1.0344x over previous
#include <cuda_runtime.h>
#include <cuda_fp16.h>
#include <cstdint>

// ECGGraphNetwork fused: single-term fp16 mma.sync, 512 threads/block.
// R14 = R13 + fp16 intermediate OUT buffer: GEMM epilogue stores half2
// (quantization moved before the graph-mix), halving epilogue/mix smem
// traffic. smem drops to ~102KB.

#define BATCH    16384
#define NLEADS   12
#define MROWS    96                 // 8 items * 12 leads
#define NTHREADS 512
#define NBLOCKS  (BATCH / 8)        // 2048

#define LDW   264                   // W chunk row stride (halves), 528B
#define LDAX  40                    // X chunk row stride (halves), 80B
#define LDH   264                   // H / OUT row stride (halves), 528B

// smem byte offsets
#define WCH      16896              // one W buffer: 32*528
#define OFFX     33792              // after 2 W buffers
#define XCH      7680               // one X buffer: 96*80
#define OFF_OUT  0                  // fp16 OUT, 96*528 = 50688 (aliases chunk bufs)
#define OFF_H    50688              // fp16 H, 96*528 = 50688
#define OFF_ADJ  101376             // 576
#define SMEMSZ   101952

// pre-converted fp16 weights, [K][N] row-major, element offsets
__device__ __half g_Wf[229376];
#define WOFF1 0
#define WOFF2 131072
#define WOFF3 196608

// sparsity of A_norm (fixed ECG graph): per-row nonzero column indices (ascending)
#define MIX_TABLES \
    const int mcnt[12] = {5,6,5,4,3,3,2,3,3,3,3,2}; \
    const int midx[12][6] = { \
        {0,1,2,3,4,0}, {0,1,2,3,4,5}, {0,1,2,3,5,0}, {0,1,2,3,0,0}, \
        {0,1,4,0,0,0}, {1,2,5,0,0,0}, {6,7,0,0,0,0}, {6,7,8,0,0,0}, \
        {7,8,9,0,0,0}, {8,9,10,0,0,0}, {9,10,11,0,0,0}, {10,11,0,0,0,0} };

// ---------------- PTX helpers ----------------

__device__ __forceinline__ uint32_t smem_u32(const void* p) {
    uint32_t a;
    asm("{ .reg .u64 t; cvta.to.shared.u64 t, %1; cvt.u32.u64 %0, t; }" : "=r"(a) : "l"(p));
    return a;
}

__device__ __forceinline__ void ldsm4(uint32_t* r, uint32_t a) {
    asm volatile("ldmatrix.sync.aligned.m8n8.x4.shared.b16 {%0,%1,%2,%3}, [%4];"
                 : "=r"(r[0]), "=r"(r[1]), "=r"(r[2]), "=r"(r[3]) : "r"(a));
}
__device__ __forceinline__ void ldsm4t(uint32_t* r, uint32_t a) {
    asm volatile("ldmatrix.sync.aligned.m8n8.x4.trans.shared.b16 {%0,%1,%2,%3}, [%4];"
                 : "=r"(r[0]), "=r"(r[1]), "=r"(r[2]), "=r"(r[3]) : "r"(a));
}

__device__ __forceinline__ void mma_fp16(float* d, const uint32_t* a,
                                         uint32_t b0, uint32_t b1) {
    asm volatile(
        "mma.sync.aligned.m16n8k16.row.col.f32.f16.f16.f32 "
        "{%0,%1,%2,%3}, {%4,%5,%6,%7}, {%8,%9}, {%0,%1,%2,%3};"
        : "+f"(d[0]), "+f"(d[1]), "+f"(d[2]), "+f"(d[3])
        : "r"(a[0]), "r"(a[1]), "r"(a[2]), "r"(a[3]), "r"(b0), "r"(b1));
}

__device__ __forceinline__ uint32_t h2u(__half2 h) { return *(uint32_t*)&h; }
__device__ __forceinline__ __half2 u2h(uint32_t u) { return *(__half2*)&u; }

// fp32 x4 -> fp16 x4 (packed uint2)
__device__ __forceinline__ uint2 pack_h4(float4 v) {
    uint2 r;
    r.x = h2u(__floats2half2_rn(v.x, v.y));
    r.y = h2u(__floats2half2_rn(v.z, v.w));
    return r;
}
// packed fp16 x4 -> fp32 x4
__device__ __forceinline__ float4 unpack_h4(uint2 p) {
    float2 a = __half22float2(u2h(p.x));
    float2 b = __half22float2(u2h(p.y));
    return make_float4(a.x, a.y, b.x, b.y);
}

// ---------------- weight fp16 convert kernel ----------------
__global__ void __launch_bounds__(512) wconv(const float* __restrict__ W1,
                                             const float* __restrict__ W2,
                                             const float* __restrict__ W3) {
    int e = (blockIdx.x * 512 + threadIdx.x) * 4;     // 112 blocks -> 229376 exact
    const float* src;
    int off;
    if (e < 131072)      { src = W1; off = e; }
    else if (e < 196608) { src = W2; off = e - 131072; }
    else                 { src = W3; off = e - 196608; }
    float4 v = *(const float4*)(src + off);
    *(uint2*)(g_Wf + e) = pack_h4(v);
}

// ---------------- adjacency ----------------
__device__ __forceinline__ void build_adj(float* As, int tid) {
    if (tid < NLEADS * NLEADS) {
        const unsigned char ci[15] = {0,0,1,0,1,2,0,1,1,2,6,7,8,9,10};
        const unsigned char cj[15] = {1,2,2,3,3,3,4,4,5,5,7,8,9,10,11};
        int i = tid / NLEADS;
        int j = tid - i * NLEADS;
        float a = (i == j) ? 2.0f : 0.0f;
        float degi = 2.0f, degj = 2.0f;
        #pragma unroll
        for (int e = 0; e < 15; e++) {
            int u = ci[e], v = cj[e];
            if ((u == i && v == j) || (u == j && v == i)) a = 1.0f;
            if (u == i || v == i) degi += 1.0f;
            if (u == j || v == j) degj += 1.0f;
        }
        As[tid] = a * rsqrtf(degi) * rsqrtf(degj);
    }
}

// ---------------- k-step: 3 m-tiles x NT n-tiles, single fp16 term ----------------
template<int NT>
__device__ __forceinline__ void kstep_mma(float (*acc)[NT][4],
                                          uint32_t aBase, int ldaB,
                                          uint32_t wBase, int lane)
{
    uint32_t b[2 * NT];
    {
        uint32_t off = (uint32_t)((lane & 15) * (LDW * 2)) + (uint32_t)(((lane >> 4) << 3) * 2);
        ldsm4t(b, wBase + off);
        if (NT == 4) ldsm4t(b + 4, wBase + off + 32);
    }
    uint32_t aoff = (uint32_t)((lane & 15) * ldaB) + (uint32_t)(((lane >> 4) << 3) * 2);
    #pragma unroll
    for (int m = 0; m < 3; m++) {
        uint32_t a[4];
        ldsm4(a, aBase + (uint32_t)(m * 16 * ldaB) + aoff);
        #pragma unroll
        for (int n = 0; n < NT; n++) mma_fp16(acc[m][n], a, b[2*n], b[2*n+1]);
    }
}

// ---------------- one GEMM layer: OUT16 = A @ W (fp16 result in smem) ----------------
// Pipelined: STS of chunk c+1 overlaps MMA of chunk c; one sync per chunk.
template<int KD, int ND, bool L1>
__device__ __forceinline__ void gemm_layer(char* smem, uint32_t sbase,
                                           const float* __restrict__ Asrc,
                                           const __half* __restrict__ Wf,
                                           int row0)
{
    constexpr int NC   = KD / 32;
    constexpr int NT   = ND / 64;      // n8-tiles per warp (4 or 2)
    constexpr int NG16 = ND / 8;       // 16B granules per W row
    constexpr int G    = 32 * NG16 / NTHREADS;   // granules per thread (2 or 1)
    const int tid = threadIdx.x, lane = tid & 31, wid = tid >> 5;
    const int mw  = wid >> 3, nw = wid & 7;
    const int m0  = mw * 48;
    const int n0  = nw * (ND / 8);

    float acc[3][NT][4] = {};
    uint4 wr[G];
    float4 xr[2];

    auto ldgW = [&](int c) {
        const __half* Wc = Wf + (size_t)c * 32 * ND;
        #pragma unroll
        for (int g = 0; g < G; g++) {
            int idx = tid + g * NTHREADS;
            int r = idx / NG16, cc = idx % NG16;
            wr[g] = *(const uint4*)(Wc + (size_t)r * ND + cc * 8);
        }
    };
    auto stsW = [&](int buf) {
        char* wb = smem + buf * WCH;
        #pragma unroll
        for (int g = 0; g < G; g++) {
            int idx = tid + g * NTHREADS;
            int r = idx / NG16, cc = idx % NG16;
            *(uint4*)(wb + r * (LDW * 2) + cc * 16) = wr[g];
        }
    };
    auto ldgX = [&](int c) {
        #pragma unroll
        for (int i = 0; i < 2; i++) {
            int f4 = tid + i * NTHREADS;
            if (f4 < MROWS * 8)
                xr[i] = *(const float4*)(Asrc + (size_t)(row0 + (f4 >> 3)) * 512
                                         + c * 32 + (f4 & 7) * 4);
        }
    };
    auto stsX = [&](int buf) {
        char* xb = smem + OFFX + buf * XCH;
        #pragma unroll
        for (int i = 0; i < 2; i++) {
            int f4 = tid + i * NTHREADS;
            if (f4 < MROWS * 8) {
                int off = (f4 >> 3) * (LDAX * 2) + (f4 & 7) * 8;
                *(uint2*)(xb + off) = pack_h4(xr[i]);
            }
        }
    };

    // prologue: chunk 0 into buf0
    ldgW(0);
    if (L1) ldgX(0);
    stsW(0);
    if (L1) stsX(0);
    __syncthreads();
    if (NC > 1) { ldgW(1); if (L1) ldgX(1); }

    for (int c = 0; c < NC; c++) {
        const int buf = c & 1;
        // stage chunk c+1 into the other buffer (overlaps this chunk's MMAs)
        if (c + 1 < NC) {
            stsW(buf ^ 1);
            if (L1) stsX(buf ^ 1);
            if (c + 2 < NC) { ldgW(c + 2); if (L1) ldgX(c + 2); }
        }
        // compute 2 k-steps of 16 from buf
        #pragma unroll
        for (int st = 0; st < 2; st++) {
            uint32_t wb = sbase + (uint32_t)(buf * WCH + st * 16 * (LDW * 2) + n0 * 2);
            if (L1) {
                uint32_t ab = sbase + (uint32_t)(OFFX + buf * XCH + m0 * (LDAX * 2) + st * 32);
                kstep_mma<NT>(acc, ab, LDAX * 2, wb, lane);
            } else {
                int kg = c * 32 + st * 16;
                uint32_t ab = sbase + (uint32_t)(OFF_H + m0 * (LDH * 2) + kg * 2);
                kstep_mma<NT>(acc, ab, LDH * 2, wb, lane);
            }
        }
        __syncthreads();
    }

    // ---- epilogue: accum -> OUT16 (fp16, stride LDH halves) ----
    #pragma unroll
    for (int m = 0; m < 3; m++)
        #pragma unroll
        for (int n = 0; n < NT; n++) {
            int r  = m0 + m * 16 + (lane >> 2);
            int cc = n0 + n * 8 + (lane & 3) * 2;
            *(uint32_t*)(smem + OFF_OUT + r * (LDH * 2) + cc * 2) =
                h2u(__floats2half2_rn(acc[m][n][0], acc[m][n][1]));
            *(uint32_t*)(smem + OFF_OUT + (r + 8) * (LDH * 2) + cc * 2) =
                h2u(__floats2half2_rn(acc[m][n][2], acc[m][n][3]));
        }
    __syncthreads();
}

// ---------------- mix + relu + fp16 store (N=256), register-blocked, sparse ----------------
__device__ __forceinline__ void mix_relu(char* smem, const float* __restrict__ bias) {
    MIX_TABLES
    const float* As = (const float*)(smem + OFF_ADJ);
    const int item = threadIdx.x >> 6;    // 0..7
    const int c4   = threadIdx.x & 63;    // 0..63

    float4 v[NLEADS];
    const char* src = smem + OFF_OUT + (item * NLEADS) * (LDH * 2) + c4 * 8;
    #pragma unroll
    for (int m = 0; m < NLEADS; m++)
        v[m] = unpack_h4(*(const uint2*)(src + m * (LDH * 2)));

    float4 bv = *(const float4*)(bias + c4 * 4);
    char* dst = smem + OFF_H + (item * NLEADS) * (LDH * 2) + c4 * 8;
    #pragma unroll
    for (int n = 0; n < NLEADS; n++) {
        float4 s = bv;
        #pragma unroll
        for (int t = 0; t < 6; t++) {
            if (t < mcnt[n]) {
                int m = midx[n][t];
                float a = As[n * NLEADS + m];
                s.x = fmaf(a, v[m].x, s.x); s.y = fmaf(a, v[m].y, s.y);
                s.z = fmaf(a, v[m].z, s.z); s.w = fmaf(a, v[m].w, s.w);
            }
        }
        s.x = fmaxf(s.x, 0.f); s.y = fmaxf(s.y, 0.f);
        s.z = fmaxf(s.z, 0.f); s.w = fmaxf(s.w, 0.f);
        *(uint2*)(dst + n * (LDH * 2)) = pack_h4(s);
    }
}

// ---------------- layer-3 mix + bias + mean/max pool (sparse) ----------------
__device__ __forceinline__ void mix_pool(char* smem, const float* __restrict__ bias,
                                         float* __restrict__ out, int bout0) {
    if (threadIdx.x >= 256) return;
    MIX_TABLES
    const float* As = (const float*)(smem + OFF_ADJ);
    int b  = threadIdx.x >> 5;      // 0..7
    int c4 = threadIdx.x & 31;      // 0..31 (128/4)
    float4 v[NLEADS];
    const char* src = smem + OFF_OUT + (b * NLEADS) * (LDH * 2) + c4 * 8;
    #pragma unroll
    for (int m = 0; m < NLEADS; m++)
        v[m] = unpack_h4(*(const uint2*)(src + m * (LDH * 2)));
    float4 bv = *(const float4*)(bias + c4 * 4);
    float4 sum = make_float4(0.f, 0.f, 0.f, 0.f);
    float4 mx  = make_float4(-3.4e38f, -3.4e38f, -3.4e38f, -3.4e38f);
    #pragma unroll
    for (int r = 0; r < NLEADS; r++) {
        float4 s = bv;
        #pragma unroll
        for (int t = 0; t < 6; t++) {
            if (t < mcnt[r]) {
                int m = midx[r][t];
                float a = As[r * NLEADS + m];
                s.x = fmaf(a, v[m].x, s.x); s.y = fmaf(a, v[m].y, s.y);
                s.z = fmaf(a, v[m].z, s.z); s.w = fmaf(a, v[m].w, s.w);
            }
        }
        sum.x += s.x; sum.y += s.y; sum.z += s.z; sum.w += s.w;
        mx.x = fmaxf(mx.x, s.x); mx.y = fmaxf(mx.y, s.y);
        mx.z = fmaxf(mx.z, s.z); mx.w = fmaxf(mx.w, s.w);
    }
    const float inv = 1.0f / 12.0f;
    float* op = out + (size_t)(bout0 + b) * 256;
    *(float4*)(op + c4 * 4)       = make_float4(sum.x*inv, sum.y*inv, sum.z*inv, sum.w*inv);
    *(float4*)(op + 128 + c4 * 4) = mx;
}

// ---------------- kernel ----------------
__global__ void __launch_bounds__(NTHREADS, 1)
ecg_mma(const float* __restrict__ x,
        const float* __restrict__ b1, const float* __restrict__ b2,
        const float* __restrict__ b3, float* __restrict__ out)
{
    extern __shared__ char smem[];
    const uint32_t sbase = smem_u32(smem);
    const int row0  = blockIdx.x * MROWS;
    const int bout0 = blockIdx.x * 8;

    build_adj((float*)(smem + OFF_ADJ), threadIdx.x);

    // layer 1: X(96x512) @ W1(512x256)
    gemm_layer<512, 256, true>(smem, sbase, x, g_Wf + WOFF1, row0);
    mix_relu(smem, b1);
    __syncthreads();
    // layer 2: H(96x256) @ W2(256x256)
    gemm_layer<256, 256, false>(smem, sbase, nullptr, g_Wf + WOFF2, row0);
    mix_relu(smem, b2);
    __syncthreads();
    // layer 3: H(96x256) @ W3(256x128) + mix + pool
    gemm_layer<256, 128, false>(smem, sbase, nullptr, g_Wf + WOFF3, row0);
    mix_pool(smem, b3, out, bout0);
}

// ---------------- launch ----------------
extern "C" void kernel_launch(void* const* d_in, const int* in_sizes, int n_in,
                              void* d_out, int out_size)
{
    const float* x  = (const float*)d_in[0];
    const float* W1 = (const float*)d_in[1];
    const float* b1 = (const float*)d_in[2];
    const float* W2 = (const float*)d_in[3];
    const float* b2 = (const float*)d_in[4];
    const float* W3 = (const float*)d_in[5];
    const float* b3 = (const float*)d_in[6];
    float* out = (float*)d_out;

    wconv<<<112, 512>>>(W1, W2, W3);

    cudaFuncSetAttribute((const void*)ecg_mma,
                         cudaFuncAttributeMaxDynamicSharedMemorySize, SMEMSZ);
    ecg_mma<<<NBLOCKS, NTHREADS, SMEMSZ>>>(x, b1, b2, b3, out);
}